// round 2
// baseline (speedup 1.0000x reference)
#include <cuda_runtime.h>
#include <cstdint>

namespace {
constexpr int kB       = 16384;
constexpr int kF       = 50;
constexpr int kE       = 64;
constexpr int kD       = 128;
constexpr int kFP      = 56;          // K padded to 7 * 8
constexpr int kK       = 7;           // k-steps of 8
constexpr int kTileW   = kFP * kE;    // 3584 words per X buffer
constexpr int kStages  = 3;
constexpr int kSlots   = 2;           // 2 b's in flight per iteration
constexpr int kThreads = 256;
constexpr int kIters   = 8;           // b-pairs per CTA
constexpr int kGrid    = kB / (2 * kIters);               // 1024 CTAs
constexpr int kSmemBytes = kStages * kSlots * kTileW * 4; // 86016 B
}

__device__ __forceinline__ uint32_t f2tf32(float x) {
    uint32_t r;
    asm("cvt.rna.tf32.f32 %0, %1;" : "=r"(r) : "f"(x));
    return r;
}

__device__ __forceinline__ void mma8(float d[4], const uint32_t a[4],
                                     uint32_t b0, uint32_t b1) {
    asm volatile(
        "mma.sync.aligned.m16n8k8.row.col.f32.tf32.tf32.f32 "
        "{%0,%1,%2,%3}, {%4,%5,%6,%7}, {%8,%9}, {%0,%1,%2,%3};\n"
        : "+f"(d[0]), "+f"(d[1]), "+f"(d[2]), "+f"(d[3])
        : "r"(a[0]), "r"(a[1]), "r"(a[2]), "r"(a[3]), "r"(b0), "r"(b1));
}

__global__ void __launch_bounds__(kThreads, 1)
InnerProduct_tf32_kernel(const float* __restrict__ X,
                         const float* __restrict__ Th,
                         float* __restrict__ out) {
    extern __shared__ float sm[];
    const int tid  = threadIdx.x;
    const int lane = tid & 31;
    const int warp = tid >> 5;
    const int g    = lane >> 2;   // groupID (0..7)
    const int q    = lane & 3;    // threadID_in_group (0..3)
    const int slot = warp >> 2;   // which b of the pair
    const int dbase = (warp & 3) << 5;  // 32 d-rows per warp

    // ---- Stage Theta into smem (zero-padded K: 50 -> 56) ----
    for (int i = tid; i < kD * kFP; i += kThreads) sm[i] = 0.f;
    __syncthreads();
    for (int i = tid; i < kD * kF; i += kThreads) {
        int d = i / kF;
        int f = i - d * kF;
        sm[d * kFP + f] = Th[i];
    }
    __syncthreads();

    // ---- Cache A fragments (Theta) in registers for the whole kernel ----
    // m16n8k8 tf32 A layout: a0:(g,q) a1:(g+8,q) a2:(g,q+4) a3:(g+8,q+4)
    uint32_t af[2][kK][4];
#pragma unroll
    for (int t = 0; t < 2; ++t)
#pragma unroll
        for (int k = 0; k < kK; ++k) {
            const int r = dbase + 16 * t + g;
            const int c = 8 * k + q;
            af[t][k][0] = f2tf32(sm[r * kFP + c]);
            af[t][k][1] = f2tf32(sm[(r + 8) * kFP + c]);
            af[t][k][2] = f2tf32(sm[r * kFP + c + 4]);
            af[t][k][3] = f2tf32(sm[(r + 8) * kFP + c + 4]);
        }
    __syncthreads();

    // ---- Zero the K-padding rows (f = 50..55) of all 6 X buffers (once).
    // cp.async only ever writes f < 50, so these stay zero. Theta pads are
    // zero too, so pad products are exactly 0 and values here just must be
    // finite.
#pragma unroll
    for (int buf = 0; buf < kStages * kSlots; ++buf)
        for (int i = tid; i < (kFP - kF) * kE; i += kThreads)
            sm[buf * kTileW + kF * kE + i] = 0.f;

    const uint32_t sbase = (uint32_t)__cvta_generic_to_shared(sm);
    const size_t bstart = (size_t)blockIdx.x * (2 * kIters);

    // X[b] tile is [F=50][E=64], e contiguous. Stored with XOR swizzle:
    // word(f,e) = f*64 + (e ^ ((f&7)<<3)); 16B blocks stay contiguous so
    // cp.async works, and both B-fragment LDS patterns are conflict-free.
    auto load_pair = [&](int j) {
        const int stage = j % kStages;
#pragma unroll
        for (int s2 = 0; s2 < kSlots; ++s2) {
            const float* src = X + (bstart + 2 * j + s2) * (size_t)(kF * kE);
            const uint32_t dbuf =
                sbase + (uint32_t)((stage * kSlots + s2) * kTileW) * 4u;
            for (int i = tid; i < (kF * kE) / 4; i += kThreads) {
                uint32_t w = (uint32_t)(4 * i) ^ ((((uint32_t)i >> 4) & 7u) << 3);
                asm volatile(
                    "cp.async.cg.shared.global [%0], [%1], 16;\n"
                    :: "r"(dbuf + w * 4u), "l"(src + 4 * (size_t)i) : "memory");
            }
        }
    };

    // ---- Prologue: prefetch first kStages-1 pairs ----
#pragma unroll
    for (int p = 0; p < kStages - 1; ++p) {
        load_pair(p);
        asm volatile("cp.async.commit_group;\n" ::: "memory");
    }

    const int xq   = q << 3;
    const int boff = (q << 6) + g;  // 64*q + g

#pragma unroll 1
    for (int it = 0; it < kIters; ++it) {
        const int jt = it + kStages - 1;
        if (jt < kIters) load_pair(jt);
        asm volatile("cp.async.commit_group;\n" ::: "memory");
        asm volatile("cp.async.wait_group %0;\n" :: "n"(kStages - 1) : "memory");
        __syncthreads();

        const int stage = it % kStages;
        const float* Xb = sm + (stage * kSlots + slot) * kTileW + boff;

        float acc[2][8][4];
#pragma unroll
        for (int t = 0; t < 2; ++t)
#pragma unroll
            for (int n = 0; n < 8; ++n)
#pragma unroll
                for (int r = 0; r < 4; ++r) acc[t][n][r] = 0.f;

        // proj[d, e] = sum_f Theta[d,f] * X[f,e]; B frag b0:(k=q, n=g),
        // b1:(k=q+4, n=g). With the swizzle, the address collapses to
        // base + 512k (+256 for b1) + ((8n) ^ 8q (^32)).
#pragma unroll
        for (int k = 0; k < kK; ++k) {
            const float* Xk = Xb + 512 * k;
#pragma unroll
            for (int n = 0; n < 8; ++n) {
                const uint32_t b0 = __float_as_uint(Xk[(8 * n) ^ xq]);
                const uint32_t b1 = __float_as_uint(Xk[256 + ((8 * n) ^ xq ^ 32)]);
                mma8(acc[0][n], af[0][k], b0, b1);
                mma8(acc[1][n], af[1][k], b0, b1);
            }
        }

        // ---- Epilogue: L_p[b,d] = sum_e proj^2, reduced within each quad.
        // D frag: c0:(g, 8n+2q) c1:(g, 8n+2q+1) c2:(g+8, ...) c3.
        const size_t bcur = bstart + 2 * it + slot;
        float* op = out + bcur * kD + dbase;
#pragma unroll
        for (int t = 0; t < 2; ++t) {
            float s0 = 0.f, s1 = 0.f;
#pragma unroll
            for (int n = 0; n < 8; ++n) {
                s0 = fmaf(acc[t][n][0], acc[t][n][0], s0);
                s0 = fmaf(acc[t][n][1], acc[t][n][1], s0);
                s1 = fmaf(acc[t][n][2], acc[t][n][2], s1);
                s1 = fmaf(acc[t][n][3], acc[t][n][3], s1);
            }
            s0 += __shfl_xor_sync(0xffffffffu, s0, 1);
            s0 += __shfl_xor_sync(0xffffffffu, s0, 2);
            s1 += __shfl_xor_sync(0xffffffffu, s1, 1);
            s1 += __shfl_xor_sync(0xffffffffu, s1, 2);
            if (q == 0) {
                op[16 * t + g]     = s0;
                op[16 * t + g + 8] = s1;
            }
        }
        __syncthreads();
    }
}

extern "C" void kernel_launch(void* const* d_in, const int* in_sizes, int n_in,
                              void* d_out, int out_size) {
    const float* X  = (const float*)d_in[0];   // inputs [16384, 50, 64] fp32
    const float* Th = (const float*)d_in[1];   // Theta  [128, 50] fp32
    float* out      = (float*)d_out;           // [16384, 128] fp32
    (void)in_sizes; (void)n_in; (void)out_size;

    cudaFuncSetAttribute(InnerProduct_tf32_kernel,
                         cudaFuncAttributeMaxDynamicSharedMemorySize, kSmemBytes);
    InnerProduct_tf32_kernel<<<kGrid, kThreads, kSmemBytes>>>(X, Th, out);
}